// round 10
// baseline (speedup 1.0000x reference)
#include <cuda_runtime.h>
#include <cuda_fp16.h>
#include <cstdint>
#include <math.h>

#define BB   64
#define NN   4096
#define DD   64
#define HH   256
#define SS   1024
#define TOT  49152   // 3 * D * H
#define WPB  24576   // half2 words per batch (3*D*H/2)

// raw hypernet output (k1 -> k2)
__device__ float g_params[BB * (size_t)TOT];
// normalized fp16 weights, half2-packed along k, XOR-swizzled (k2 -> k3)
__device__ uint32_t g_wT[BB * (size_t)WPB];

// ======================= helpers =======================
__device__ __forceinline__ float tanha(float x) {
    float y;
    asm("tanh.approx.f32 %0, %1;" : "=f"(y) : "f"(x));
    return y;
}
__device__ __forceinline__ uint32_t pack2(float lo, float hi) {
    __half2 h = __floats2half2_rn(lo, hi);
    return *(uint32_t*)&h;
}
__device__ __forceinline__ uint32_t smem_u32(const void* p) {
    uint32_t a;
    asm("{ .reg .u64 t; cvta.to.shared.u64 t, %1; cvt.u32.u64 %0, t; }" : "=r"(a) : "l"(p));
    return a;
}
__device__ __forceinline__ void cpa16(uint32_t dst, const void* src) {
    asm volatile("cp.async.cg.shared.global [%0], [%1], 16;" :: "r"(dst), "l"(src));
}
#define CP_COMMIT() asm volatile("cp.async.commit_group;" ::: "memory")
#define CP_WAIT0()  asm volatile("cp.async.wait_group 0;" ::: "memory")
#define CP_WAIT1()  asm volatile("cp.async.wait_group 1;" ::: "memory")

// D += A * B  (m16n8k8, tf32 inputs, fp32 accum) — kernel 1
__device__ __forceinline__ void mma_tf32(float* d, const uint32_t* a, uint32_t b0, uint32_t b1) {
    asm volatile("mma.sync.aligned.m16n8k8.row.col.f32.tf32.tf32.f32 "
                 "{%0,%1,%2,%3}, {%4,%5,%6,%7}, {%8,%9}, {%0,%1,%2,%3};"
                 : "+f"(d[0]), "+f"(d[1]), "+f"(d[2]), "+f"(d[3])
                 : "r"(a[0]), "r"(a[1]), "r"(a[2]), "r"(a[3]), "r"(b0), "r"(b1));
}
// D += A * B  (m16n8k16, fp16 inputs, fp32 accum) — kernel 3
__device__ __forceinline__ void mma_f16(float* d, const uint32_t* a, uint32_t b0, uint32_t b1) {
    asm volatile("mma.sync.aligned.m16n8k16.row.col.f32.f16.f16.f32 "
                 "{%0,%1,%2,%3}, {%4,%5,%6,%7}, {%8,%9}, {%0,%1,%2,%3};"
                 : "+f"(d[0]), "+f"(d[1]), "+f"(d[2]), "+f"(d[3])
                 : "r"(a[0]), "r"(a[1]), "r"(a[2]), "r"(a[3]), "r"(b0), "r"(b1));
}

// ======================= kernel 1: hypernet GEMM via mma.sync tf32 (reverted, proven 59us) =======================
#define K1_SMEM ((2 * 64 * 36 + 2 * 32 * 136) * 4)   // 53248 B

__global__ __launch_bounds__(256) void k1_mma(const float* __restrict__ s,
                                              const float* __restrict__ W,
                                              const float* __restrict__ bias) {
    extern __shared__ float sk[];
    float* sA = sk;              // 2 * 2304
    float* sB = sk + 4608;       // 2 * 4352
    const int n0  = blockIdx.x * 128;
    const int tid = threadIdx.x;
    const int w = tid >> 5, lane = tid & 31;
    const int r = lane >> 2, q = lane & 3;
    const int m0 = (w & 1) * 32, nw = (w >> 1) * 32;
    const uint32_t sbA = smem_u32(sA), sbB = smem_u32(sB);

    #define K1_LOAD(st, k0) do {                                                   \
        _Pragma("unroll")                                                          \
        for (int i = 0; i < 2; i++) {                                              \
            int c = tid + i * 256;                                                 \
            int row = c >> 3, cc = c & 7;                                          \
            cpa16(sbA + (uint32_t)((st) * 2304 + row * 36 + cc * 4) * 4,           \
                  s + (size_t)row * SS + (k0) + cc * 4);                           \
        }                                                                          \
        _Pragma("unroll")                                                          \
        for (int i = 0; i < 4; i++) {                                              \
            int c = tid + i * 256;                                                 \
            int row = c >> 5, cc = c & 31;                                         \
            cpa16(sbB + (uint32_t)((st) * 4352 + row * 136 + cc * 4) * 4,          \
                  W + (size_t)((k0) + row) * TOT + n0 + cc * 4);                   \
        }                                                                          \
    } while (0)

    float acc[2][4][4];
    #pragma unroll
    for (int mf = 0; mf < 2; mf++)
        #pragma unroll
        for (int nf = 0; nf < 4; nf++)
            acc[mf][nf][0] = acc[mf][nf][1] = acc[mf][nf][2] = acc[mf][nf][3] = 0.f;

    K1_LOAD(0, 0);  CP_COMMIT();
    K1_LOAD(1, 32); CP_COMMIT();

    for (int ks = 0; ks < 32; ks++) {
        CP_WAIT1();
        __syncthreads();
        const int st = ks & 1;
        const float* A  = sA + st * 2304;
        const float* Bp = sB + st * 4352;
        #pragma unroll
        for (int kk = 0; kk < 4; kk++) {
            uint32_t a[2][4];
            #pragma unroll
            for (int mf = 0; mf < 2; mf++) {
                const int mr = m0 + mf * 16 + r;
                a[mf][0] = __float_as_uint(A[mr * 36 + kk * 8 + q]);
                a[mf][1] = __float_as_uint(A[(mr + 8) * 36 + kk * 8 + q]);
                a[mf][2] = __float_as_uint(A[mr * 36 + kk * 8 + q + 4]);
                a[mf][3] = __float_as_uint(A[(mr + 8) * 36 + kk * 8 + q + 4]);
            }
            #pragma unroll
            for (int nf = 0; nf < 4; nf++) {
                const int cb = nw + nf * 8 + r;
                uint32_t b0 = __float_as_uint(Bp[(kk * 8 + q) * 136 + cb]);
                uint32_t b1 = __float_as_uint(Bp[(kk * 8 + q + 4) * 136 + cb]);
                mma_tf32(acc[0][nf], a[0], b0, b1);
                mma_tf32(acc[1][nf], a[1], b0, b1);
            }
        }
        __syncthreads();
        const int kn = (ks + 2) * 32;
        if (kn < SS) { K1_LOAD(st, kn); }
        CP_COMMIT();
    }

    #pragma unroll
    for (int nf = 0; nf < 4; nf++) {
        float2 bv = *(const float2*)(bias + n0 + nw + nf * 8 + 2 * q);
        #pragma unroll
        for (int mf = 0; mf < 2; mf++) {
            const int mr = m0 + mf * 16 + r;
            float* o0 = g_params + (size_t)mr * TOT + n0 + nw + nf * 8 + 2 * q;
            *(float2*)o0 = make_float2(acc[mf][nf][0] + bv.x, acc[mf][nf][1] + bv.y);
            float* o1 = g_params + (size_t)(mr + 8) * TOT + n0 + nw + nf * 8 + 2 * q;
            *(float2*)o1 = make_float2(acc[mf][nf][2] + bv.x, acc[mf][nf][3] + bv.y);
        }
    }
    #undef K1_LOAD
}

// ======================= kernel 2: normalize -> fp16 half2 swizzled layout =======================
__global__ __launch_bounds__(256) void k2_normalize() {
    __shared__ float sinv[256];
    __shared__ float part[4][64];
    const int b = blockIdx.x, tid = threadIdx.x;
    const float* P = g_params + (size_t)b * TOT;
    uint32_t* dst = g_wT + (size_t)b * WPB;

    #pragma unroll
    for (int m = 0; m < 2; m++) {
        const float* src = P + m * 16384;
        {
            float ss = 0.f;
            #pragma unroll 8
            for (int d = 0; d < 64; d++) { float v = src[d * 256 + tid]; ss += v * v; }
            sinv[tid] = 1.f / fmaxf(sqrtf(ss), 1e-12f);
        }
        __syncthreads();
        for (int idx = tid; idx < 8192; idx += 256) {
            int kp = idx >> 8, h = idx & 255;
            float inv = sinv[h];
            float a = src[(2 * kp) * 256 + h] * inv;
            float c = src[(2 * kp + 1) * 256 + h] * inv;
            dst[m * 8192 + kp * 256 + (h ^ ((kp & 3) << 3))] = pack2(a, c);
        }
        __syncthreads();
    }
    {
        const float* src = P + 32768;
        int q = tid >> 6, dd = tid & 63;
        float ss = 0.f;
        #pragma unroll 8
        for (int h = q * 64; h < q * 64 + 64; h++) { float v = src[h * 64 + dd]; ss += v * v; }
        part[q][dd] = ss;
        __syncthreads();
        if (tid < 64)
            sinv[tid] = 1.f / fmaxf(sqrtf(part[0][tid] + part[1][tid] + part[2][tid] + part[3][tid]), 1e-12f);
        __syncthreads();
        for (int idx = tid; idx < 8192; idx += 256) {
            int hp = idx >> 6, d = idx & 63;
            float inv = sinv[d];
            float a = src[(2 * hp) * 64 + d] * inv;
            float c = src[(2 * hp + 1) * 64 + d] * inv;
            dst[16384 + hp * 64 + (d ^ ((hp & 3) << 3))] = pack2(a, c);
        }
    }
}

// ======================= kernel 3: fp16 mma fused MLP, 512 threads (4 warps/SMSP) =======================
// grid 1024: 16 CTAs/batch x 4 groups of 64 rows.
// 16 warps: hq = w>>2 (64-col H quarter), mw = w&3 (16-row m-tile).
// smem: weights 24576 w | xn [64][36] w | out buffers 2 x [64][68] fp32
#define K3_SMEM ((24576 + 2304 + 8704) * 4)   // 142336 B

__global__ __launch_bounds__(512, 1) void k3_main(const float* __restrict__ x,
                                                  const float* __restrict__ scale,
                                                  float* __restrict__ out) {
    extern __shared__ uint32_t su[];
    uint32_t* xnw = su + 24576;              // [64][36] half2 words
    float* buf0 = (float*)(su + 26880);      // [64][68]
    float* buf1 = buf0 + 4352;               // [64][68]
    const int tid = threadIdx.x, w = tid >> 5, lane = tid & 31;
    const int b = blockIdx.x >> 4;
    const int gbase = (blockIdx.x & 15) * 4;
    const int hq = w >> 2, mw = w & 3, m0 = mw * 16;
    const int nb = hq * 64;
    const int r = lane >> 2, q = lane & 3, q8 = q << 3;
    const uint32_t sb = smem_u32(su);

    // prefetch weights via cp.async (overlaps with group-0 RMS staging)
    {
        const uint32_t* wsrc = g_wT + (size_t)b * WPB;
        #pragma unroll 3
        for (int i = tid; i < 6144; i += 512)
            cpa16(sb + (uint32_t)i * 16, wsrc + i * 4);
        CP_COMMIT();
    }
    const int srow = tid >> 3, sqc = (tid & 7) * 8;
    const float4 scA = *(const float4*)(scale + sqc);
    const float4 scB = *(const float4*)(scale + sqc + 4);

    const uint32_t* Wg = su;
    const uint32_t* Wv = su + 8192;
    const uint32_t* Wf = su + 16384;

    for (int g = 0; g < 4; g++) {
        const int row0 = (gbase + g) * 64;

        // ---- stage RMSNorm'd xn (fp16 RNE); residual stays in regs ----
        float4 xres0, xres1;
        {
            const float4* xr = (const float4*)(x + ((size_t)b * NN + row0 + srow) * DD + sqc);
            xres0 = xr[0]; xres1 = xr[1];
            float ssq = xres0.x * xres0.x + xres0.y * xres0.y + xres0.z * xres0.z + xres0.w * xres0.w
                      + xres1.x * xres1.x + xres1.y * xres1.y + xres1.z * xres1.z + xres1.w * xres1.w;
            ssq += __shfl_xor_sync(0xffffffffu, ssq, 1);
            ssq += __shfl_xor_sync(0xffffffffu, ssq, 2);
            ssq += __shfl_xor_sync(0xffffffffu, ssq, 4);
            const float rr = rsqrtf(ssq * (1.0f / 64.0f) + 1e-6f);
            uint32_t* xd = xnw + srow * 36 + (tid & 7) * 4;
            xd[0] = pack2(xres0.x * rr * scA.x, xres0.y * rr * scA.y);
            xd[1] = pack2(xres0.z * rr * scA.z, xres0.w * rr * scA.w);
            xd[2] = pack2(xres1.x * rr * scB.x, xres1.y * rr * scB.y);
            xd[3] = pack2(xres1.z * rr * scB.z, xres1.w * rr * scB.w);
        }
        if (g == 0) { CP_WAIT0(); }
        __syncthreads();

        // ---- cache A fragments for all 4 k16 tiles (16 regs) ----
        uint32_t xa[4][4];
        {
            const uint32_t* xb = xnw + (m0 + r) * 36;
            #pragma unroll
            for (int kt = 0; kt < 4; kt++) {
                xa[kt][0] = xb[kt * 8 + q];
                xa[kt][1] = xb[8 * 36 + kt * 8 + q];
                xa[kt][2] = xb[kt * 8 + q + 4];
                xa[kt][3] = xb[8 * 36 + kt * 8 + q + 4];
            }
        }

        float oacc[8][4];
        #pragma unroll
        for (int i = 0; i < 8; i++) { oacc[i][0] = oacc[i][1] = oacc[i][2] = oacc[i][3] = 0.f; }

        // ---- 4 slices of 16 H-cols: MMA1 -> silu -> MMA2 ----
        #pragma unroll
        for (int ch2 = 0; ch2 < 4; ch2++) {
            const int nc = nb + ch2 * 16;
            float ga[2][4], va[2][4];
            #pragma unroll
            for (int i = 0; i < 2; i++) {
                ga[i][0] = ga[i][1] = ga[i][2] = ga[i][3] = 0.f;
                va[i][0] = va[i][1] = va[i][2] = va[i][3] = 0.f;
            }
            const int c0 = (nc ^ q8) + r;
            const int c1 = ((nc + 8) ^ q8) + r;
            #pragma unroll
            for (int kt = 0; kt < 4; kt++) {
                const uint32_t* g0 = Wg + (kt * 8 + q) * 256;
                const uint32_t* g1 = Wg + (kt * 8 + q + 4) * 256;
                const uint32_t* v0 = Wv + (kt * 8 + q) * 256;
                const uint32_t* v1 = Wv + (kt * 8 + q + 4) * 256;
                mma_f16(ga[0], xa[kt], g0[c0], g1[c0]);
                mma_f16(ga[1], xa[kt], g0[c1], g1[c1]);
                mma_f16(va[0], xa[kt], v0[c0], v1[c0]);
                mma_f16(va[1], xa[kt], v0[c1], v1[c1]);
            }
            float h00 = 0.5f * ga[0][0] * (1.f + tanha(0.5f * ga[0][0])) * va[0][0];
            float h01 = 0.5f * ga[0][1] * (1.f + tanha(0.5f * ga[0][1])) * va[0][1];
            float h02 = 0.5f * ga[0][2] * (1.f + tanha(0.5f * ga[0][2])) * va[0][2];
            float h03 = 0.5f * ga[0][3] * (1.f + tanha(0.5f * ga[0][3])) * va[0][3];
            float h10 = 0.5f * ga[1][0] * (1.f + tanha(0.5f * ga[1][0])) * va[1][0];
            float h11 = 0.5f * ga[1][1] * (1.f + tanha(0.5f * ga[1][1])) * va[1][1];
            float h12 = 0.5f * ga[1][2] * (1.f + tanha(0.5f * ga[1][2])) * va[1][2];
            float h13 = 0.5f * ga[1][3] * (1.f + tanha(0.5f * ga[1][3])) * va[1][3];
            uint32_t ha[4];
            ha[0] = pack2(h00, h01);
            ha[1] = pack2(h02, h03);
            ha[2] = pack2(h10, h11);
            ha[3] = pack2(h12, h13);
            const int hp0 = (nb >> 1) + ch2 * 8;
            const uint32_t* f0 = Wf + (hp0 + q) * 64;
            const uint32_t* f1 = Wf + (hp0 + q + 4) * 64;
            #pragma unroll
            for (int dt = 0; dt < 8; dt++) {
                const int c = ((dt * 8) ^ q8) + r;
                mma_f16(oacc[dt], ha, f0[c], f1[c]);
            }
        }

        // ---- two-round reduction over the 4 H quarters ----
        if (hq < 2) {
            float* bufw = buf0 + hq * 4352;
            #pragma unroll
            for (int dt = 0; dt < 8; dt++) {
                *(float2*)&bufw[(m0 + r) * 68 + dt * 8 + 2 * q]     = make_float2(oacc[dt][0], oacc[dt][1]);
                *(float2*)&bufw[(m0 + r + 8) * 68 + dt * 8 + 2 * q] = make_float2(oacc[dt][2], oacc[dt][3]);
            }
        }
        __syncthreads();
        if (hq >= 2) {
            float* bufw = buf0 + (hq - 2) * 4352;
            #pragma unroll
            for (int dt = 0; dt < 8; dt++) {
                float2 p0 = *(float2*)&bufw[(m0 + r) * 68 + dt * 8 + 2 * q];
                float2 p1 = *(float2*)&bufw[(m0 + r + 8) * 68 + dt * 8 + 2 * q];
                p0.x += oacc[dt][0]; p0.y += oacc[dt][1];
                p1.x += oacc[dt][2]; p1.y += oacc[dt][3];
                *(float2*)&bufw[(m0 + r) * 68 + dt * 8 + 2 * q]     = p0;
                *(float2*)&bufw[(m0 + r + 8) * 68 + dt * 8 + 2 * q] = p1;
            }
        }
        __syncthreads();

        // ---- final: buf0 + buf1 + residual -> gmem ----
        {
            float4 a0 = *(float4*)&buf0[srow * 68 + sqc];
            float4 a1 = *(float4*)&buf0[srow * 68 + sqc + 4];
            float4 c0 = *(float4*)&buf1[srow * 68 + sqc];
            float4 c1 = *(float4*)&buf1[srow * 68 + sqc + 4];
            float* orow = out + ((size_t)b * NN + row0 + srow) * DD + sqc;
            *(float4*)orow       = make_float4(a0.x + c0.x + xres0.x, a0.y + c0.y + xres0.y,
                                               a0.z + c0.z + xres0.z, a0.w + c0.w + xres0.w);
            *(float4*)(orow + 4) = make_float4(a1.x + c1.x + xres1.x, a1.y + c1.y + xres1.y,
                                               a1.z + c1.z + xres1.z, a1.w + c1.w + xres1.w);
        }
    }
}

// ======================= launch =======================
extern "C" void kernel_launch(void* const* d_in, const int* in_sizes, int n_in,
                              void* d_out, int out_size) {
    const float* x     = (const float*)d_in[0];
    const float* s     = (const float*)d_in[1];
    const float* W     = (const float*)d_in[2];
    const float* bias  = (const float*)d_in[3];
    const float* scale = (const float*)d_in[4];
    float* out = (float*)d_out;

    cudaFuncSetAttribute(k1_mma, cudaFuncAttributeMaxDynamicSharedMemorySize, K1_SMEM);
    k1_mma<<<dim3(TOT / 128), 256, K1_SMEM>>>(s, W, bias);

    k2_normalize<<<dim3(BB), 256>>>();

    cudaFuncSetAttribute(k3_main, cudaFuncAttributeMaxDynamicSharedMemorySize, K3_SMEM);
    k3_main<<<dim3(1024), 512, K3_SMEM>>>(x, scale, out);
}

// round 11
// speedup vs baseline: 1.1874x; 1.1874x over previous
#include <cuda_runtime.h>
#include <cuda_fp16.h>
#include <cstdint>
#include <math.h>

#define BB   64
#define NN   4096
#define DD   64
#define HH   256
#define SS   1024
#define TOT  49152   // 3 * D * H
#define WPB  24576   // half2 words per batch (3*D*H/2)

// raw hypernet output (k1 -> k2)
__device__ float g_params[BB * (size_t)TOT];
// normalized fp16 weights, half2-packed along k, XOR-swizzled (k2 -> k3)
__device__ uint32_t g_wT[BB * (size_t)WPB];

// ======================= helpers =======================
__device__ __forceinline__ float tanha(float x) {
    float y;
    asm("tanh.approx.f32 %0, %1;" : "=f"(y) : "f"(x));
    return y;
}
__device__ __forceinline__ uint32_t pack2(float lo, float hi) {
    __half2 h = __floats2half2_rn(lo, hi);
    return *(uint32_t*)&h;
}
__device__ __forceinline__ uint32_t smem_u32(const void* p) {
    uint32_t a;
    asm("{ .reg .u64 t; cvta.to.shared.u64 t, %1; cvt.u32.u64 %0, t; }" : "=r"(a) : "l"(p));
    return a;
}
__device__ __forceinline__ void cpa16(uint32_t dst, const void* src) {
    asm volatile("cp.async.cg.shared.global [%0], [%1], 16;" :: "r"(dst), "l"(src));
}
#define CP_COMMIT() asm volatile("cp.async.commit_group;" ::: "memory")
#define CP_WAIT0()  asm volatile("cp.async.wait_group 0;" ::: "memory")
#define CP_WAIT1()  asm volatile("cp.async.wait_group 1;" ::: "memory")

// D += A * B  (m16n8k8, tf32 inputs, fp32 accum) — kernel 1
__device__ __forceinline__ void mma_tf32(float* d, const uint32_t* a, uint32_t b0, uint32_t b1) {
    asm volatile("mma.sync.aligned.m16n8k8.row.col.f32.tf32.tf32.f32 "
                 "{%0,%1,%2,%3}, {%4,%5,%6,%7}, {%8,%9}, {%0,%1,%2,%3};"
                 : "+f"(d[0]), "+f"(d[1]), "+f"(d[2]), "+f"(d[3])
                 : "r"(a[0]), "r"(a[1]), "r"(a[2]), "r"(a[3]), "r"(b0), "r"(b1));
}
// D += A * B  (m16n8k16, fp16 inputs, fp32 accum) — kernel 3
__device__ __forceinline__ void mma_f16(float* d, const uint32_t* a, uint32_t b0, uint32_t b1) {
    asm volatile("mma.sync.aligned.m16n8k16.row.col.f32.f16.f16.f32 "
                 "{%0,%1,%2,%3}, {%4,%5,%6,%7}, {%8,%9}, {%0,%1,%2,%3};"
                 : "+f"(d[0]), "+f"(d[1]), "+f"(d[2]), "+f"(d[3])
                 : "r"(a[0]), "r"(a[1]), "r"(a[2]), "r"(a[3]), "r"(b0), "r"(b1));
}

// ======================= kernel 1: hypernet GEMM via mma.sync tf32 (frozen, 58us) =======================
#define K1_SMEM ((2 * 64 * 36 + 2 * 32 * 136) * 4)   // 53248 B

__global__ __launch_bounds__(256) void k1_mma(const float* __restrict__ s,
                                              const float* __restrict__ W,
                                              const float* __restrict__ bias) {
    extern __shared__ float sk[];
    float* sA = sk;              // 2 * 2304
    float* sB = sk + 4608;       // 2 * 4352
    const int n0  = blockIdx.x * 128;
    const int tid = threadIdx.x;
    const int w = tid >> 5, lane = tid & 31;
    const int r = lane >> 2, q = lane & 3;
    const int m0 = (w & 1) * 32, nw = (w >> 1) * 32;
    const uint32_t sbA = smem_u32(sA), sbB = smem_u32(sB);

    #define K1_LOAD(st, k0) do {                                                   \
        _Pragma("unroll")                                                          \
        for (int i = 0; i < 2; i++) {                                              \
            int c = tid + i * 256;                                                 \
            int row = c >> 3, cc = c & 7;                                          \
            cpa16(sbA + (uint32_t)((st) * 2304 + row * 36 + cc * 4) * 4,           \
                  s + (size_t)row * SS + (k0) + cc * 4);                           \
        }                                                                          \
        _Pragma("unroll")                                                          \
        for (int i = 0; i < 4; i++) {                                              \
            int c = tid + i * 256;                                                 \
            int row = c >> 5, cc = c & 31;                                         \
            cpa16(sbB + (uint32_t)((st) * 4352 + row * 136 + cc * 4) * 4,          \
                  W + (size_t)((k0) + row) * TOT + n0 + cc * 4);                   \
        }                                                                          \
    } while (0)

    float acc[2][4][4];
    #pragma unroll
    for (int mf = 0; mf < 2; mf++)
        #pragma unroll
        for (int nf = 0; nf < 4; nf++)
            acc[mf][nf][0] = acc[mf][nf][1] = acc[mf][nf][2] = acc[mf][nf][3] = 0.f;

    K1_LOAD(0, 0);  CP_COMMIT();
    K1_LOAD(1, 32); CP_COMMIT();

    for (int ks = 0; ks < 32; ks++) {
        CP_WAIT1();
        __syncthreads();
        const int st = ks & 1;
        const float* A  = sA + st * 2304;
        const float* Bp = sB + st * 4352;
        #pragma unroll
        for (int kk = 0; kk < 4; kk++) {
            uint32_t a[2][4];
            #pragma unroll
            for (int mf = 0; mf < 2; mf++) {
                const int mr = m0 + mf * 16 + r;
                a[mf][0] = __float_as_uint(A[mr * 36 + kk * 8 + q]);
                a[mf][1] = __float_as_uint(A[(mr + 8) * 36 + kk * 8 + q]);
                a[mf][2] = __float_as_uint(A[mr * 36 + kk * 8 + q + 4]);
                a[mf][3] = __float_as_uint(A[(mr + 8) * 36 + kk * 8 + q + 4]);
            }
            #pragma unroll
            for (int nf = 0; nf < 4; nf++) {
                const int cb = nw + nf * 8 + r;
                uint32_t b0 = __float_as_uint(Bp[(kk * 8 + q) * 136 + cb]);
                uint32_t b1 = __float_as_uint(Bp[(kk * 8 + q + 4) * 136 + cb]);
                mma_tf32(acc[0][nf], a[0], b0, b1);
                mma_tf32(acc[1][nf], a[1], b0, b1);
            }
        }
        __syncthreads();
        const int kn = (ks + 2) * 32;
        if (kn < SS) { K1_LOAD(st, kn); }
        CP_COMMIT();
    }

    #pragma unroll
    for (int nf = 0; nf < 4; nf++) {
        float2 bv = *(const float2*)(bias + n0 + nw + nf * 8 + 2 * q);
        #pragma unroll
        for (int mf = 0; mf < 2; mf++) {
            const int mr = m0 + mf * 16 + r;
            float* o0 = g_params + (size_t)mr * TOT + n0 + nw + nf * 8 + 2 * q;
            *(float2*)o0 = make_float2(acc[mf][nf][0] + bv.x, acc[mf][nf][1] + bv.y);
            float* o1 = g_params + (size_t)(mr + 8) * TOT + n0 + nw + nf * 8 + 2 * q;
            *(float2*)o1 = make_float2(acc[mf][nf][2] + bv.x, acc[mf][nf][3] + bv.y);
        }
    }
    #undef K1_LOAD
}

// ======================= kernel 2: normalize -> fp16 half2 swizzled layout (frozen) =======================
__global__ __launch_bounds__(256) void k2_normalize() {
    __shared__ float sinv[256];
    __shared__ float part[4][64];
    const int b = blockIdx.x, tid = threadIdx.x;
    const float* P = g_params + (size_t)b * TOT;
    uint32_t* dst = g_wT + (size_t)b * WPB;

    #pragma unroll
    for (int m = 0; m < 2; m++) {
        const float* src = P + m * 16384;
        {
            float ss = 0.f;
            #pragma unroll 8
            for (int d = 0; d < 64; d++) { float v = src[d * 256 + tid]; ss += v * v; }
            sinv[tid] = 1.f / fmaxf(sqrtf(ss), 1e-12f);
        }
        __syncthreads();
        for (int idx = tid; idx < 8192; idx += 256) {
            int kp = idx >> 8, h = idx & 255;
            float inv = sinv[h];
            float a = src[(2 * kp) * 256 + h] * inv;
            float c = src[(2 * kp + 1) * 256 + h] * inv;
            dst[m * 8192 + kp * 256 + (h ^ ((kp & 3) << 3))] = pack2(a, c);
        }
        __syncthreads();
    }
    {
        const float* src = P + 32768;
        int q = tid >> 6, dd = tid & 63;
        float ss = 0.f;
        #pragma unroll 8
        for (int h = q * 64; h < q * 64 + 64; h++) { float v = src[h * 64 + dd]; ss += v * v; }
        part[q][dd] = ss;
        __syncthreads();
        if (tid < 64)
            sinv[tid] = 1.f / fmaxf(sqrtf(part[0][tid] + part[1][tid] + part[2][tid] + part[3][tid]), 1e-12f);
        __syncthreads();
        for (int idx = tid; idx < 8192; idx += 256) {
            int hp = idx >> 6, d = idx & 63;
            float inv = sinv[d];
            float a = src[(2 * hp) * 64 + d] * inv;
            float c = src[(2 * hp + 1) * 64 + d] * inv;
            dst[16384 + hp * 64 + (d ^ ((hp & 3) << 3))] = pack2(a, c);
        }
    }
}

// ======================= kernel 3: fp16 mma, warp = 32-row m-pair x full H (no reduction) =======================
// grid 1024: b = blk>>4, rows [ (blk&15)*256, +256 ). 8 warps x 32 rows.
// smem: weights 24576 w | scale 64 w | xn [256][36] w
#define K3_XN_OFF 24640
#define K3_SMEM   ((24576 + 64 + 9216) * 4)   // 135424 B

__global__ __launch_bounds__(256, 1) void k3_main(const float* __restrict__ x,
                                                  const float* __restrict__ scale,
                                                  float* __restrict__ out) {
    extern __shared__ uint32_t su[];
    float* ssc = (float*)(su + 24576);       // scale [64]
    uint32_t* xnw = su + K3_XN_OFF;          // [256][36] half2 words
    const int tid = threadIdx.x, w = tid >> 5, lane = tid & 31;
    const int b = blockIdx.x >> 4;
    const int row0 = (blockIdx.x & 15) * 256;
    const int m0 = w * 32;
    const int r = lane >> 2, q = lane & 3, q8 = q << 3;
    const uint32_t sb = smem_u32(su);

    // prefetch weights via cp.async (overlaps with staging)
    {
        const uint32_t* wsrc = g_wT + (size_t)b * WPB;
        #pragma unroll 6
        for (int i = tid; i < 6144; i += 256)
            cpa16(sb + (uint32_t)i * 16, wsrc + i * 4);
        CP_COMMIT();
    }
    if (tid < 64) ssc[tid] = scale[tid];
    __syncthreads();

    // ---- stage RMSNorm'd xn: one thread per row ----
    {
        const float4* xr = (const float4*)(x + ((size_t)b * NN + row0 + tid) * DD);
        float4 v[16];
        float ssq = 0.f;
        #pragma unroll
        for (int i = 0; i < 16; i++) {
            v[i] = xr[i];
            ssq += v[i].x * v[i].x + v[i].y * v[i].y + v[i].z * v[i].z + v[i].w * v[i].w;
        }
        const float rr = rsqrtf(ssq * (1.0f / 64.0f) + 1e-6f);
        uint32_t* xd = xnw + tid * 36;
        #pragma unroll
        for (int i = 0; i < 8; i++) {
            float4 a = v[2 * i], c = v[2 * i + 1];
            float4 sA = *(const float4*)&ssc[8 * i];
            float4 sB = *(const float4*)&ssc[8 * i + 4];
            uint4 o;
            o.x = pack2(a.x * rr * sA.x, a.y * rr * sA.y);
            o.y = pack2(a.z * rr * sA.z, a.w * rr * sA.w);
            o.z = pack2(c.x * rr * sB.x, c.y * rr * sB.y);
            o.w = pack2(c.z * rr * sB.z, c.w * rr * sB.w);
            *(uint4*)&xd[4 * i] = o;
        }
    }
    CP_WAIT0();
    __syncthreads();

    const uint32_t* Wg = su;
    const uint32_t* Wv = su + 8192;
    const uint32_t* Wf = su + 16384;

    // ---- cache A fragments: 4 k16 tiles x 2 m-frags (32 regs) ----
    uint32_t xa[4][2][4];
    #pragma unroll
    for (int kt = 0; kt < 4; kt++) {
        #pragma unroll
        for (int mf = 0; mf < 2; mf++) {
            const uint32_t* xb = xnw + (m0 + mf * 16 + r) * 36 + kt * 8 + q;
            xa[kt][mf][0] = xb[0];
            xa[kt][mf][1] = xb[8 * 36];
            xa[kt][mf][2] = xb[4];
            xa[kt][mf][3] = xb[8 * 36 + 4];
        }
    }

    float oacc[2][8][4];
    #pragma unroll
    for (int mf = 0; mf < 2; mf++)
        #pragma unroll
        for (int i = 0; i < 8; i++)
            oacc[mf][i][0] = oacc[mf][i][1] = oacc[mf][i][2] = oacc[mf][i][3] = 0.f;

    // ---- 16 chunks of 16 H-cols: MMA1 (1 LDS/mma via m-pair reuse) -> silu -> MMA2 ----
    #pragma unroll 4
    for (int ch = 0; ch < 16; ch++) {
        const int nc = ch * 16;
        float ga[2][2][4], va[2][2][4];
        #pragma unroll
        for (int mf = 0; mf < 2; mf++)
            #pragma unroll
            for (int nt = 0; nt < 2; nt++) {
                ga[mf][nt][0] = ga[mf][nt][1] = ga[mf][nt][2] = ga[mf][nt][3] = 0.f;
                va[mf][nt][0] = va[mf][nt][1] = va[mf][nt][2] = va[mf][nt][3] = 0.f;
            }
        const int c0 = (nc ^ q8) + r;
        const int c1 = ((nc + 8) ^ q8) + r;
        #pragma unroll
        for (int kt = 0; kt < 4; kt++) {
            const uint32_t* g0 = Wg + (kt * 8 + q) * 256;
            const uint32_t* g1 = Wg + (kt * 8 + q + 4) * 256;
            const uint32_t* v0 = Wv + (kt * 8 + q) * 256;
            const uint32_t* v1 = Wv + (kt * 8 + q + 4) * 256;
            uint32_t gb00 = g0[c0], gb10 = g1[c0], gb01 = g0[c1], gb11 = g1[c1];
            uint32_t vb00 = v0[c0], vb10 = v1[c0], vb01 = v0[c1], vb11 = v1[c1];
            #pragma unroll
            for (int mf = 0; mf < 2; mf++) {
                mma_f16(ga[mf][0], xa[kt][mf], gb00, gb10);
                mma_f16(ga[mf][1], xa[kt][mf], gb01, gb11);
                mma_f16(va[mf][0], xa[kt][mf], vb00, vb10);
                mma_f16(va[mf][1], xa[kt][mf], vb01, vb11);
            }
        }

        const int hp0 = ch * 8;
        const uint32_t* f0 = Wf + (hp0 + q) * 64;
        const uint32_t* f1 = Wf + (hp0 + q + 4) * 64;
        uint32_t ha[2][4];
        #pragma unroll
        for (int mf = 0; mf < 2; mf++) {
            float h00 = 0.5f * ga[mf][0][0] * (1.f + tanha(0.5f * ga[mf][0][0])) * va[mf][0][0];
            float h01 = 0.5f * ga[mf][0][1] * (1.f + tanha(0.5f * ga[mf][0][1])) * va[mf][0][1];
            float h02 = 0.5f * ga[mf][0][2] * (1.f + tanha(0.5f * ga[mf][0][2])) * va[mf][0][2];
            float h03 = 0.5f * ga[mf][0][3] * (1.f + tanha(0.5f * ga[mf][0][3])) * va[mf][0][3];
            float h10 = 0.5f * ga[mf][1][0] * (1.f + tanha(0.5f * ga[mf][1][0])) * va[mf][1][0];
            float h11 = 0.5f * ga[mf][1][1] * (1.f + tanha(0.5f * ga[mf][1][1])) * va[mf][1][1];
            float h12 = 0.5f * ga[mf][1][2] * (1.f + tanha(0.5f * ga[mf][1][2])) * va[mf][1][2];
            float h13 = 0.5f * ga[mf][1][3] * (1.f + tanha(0.5f * ga[mf][1][3])) * va[mf][1][3];
            ha[mf][0] = pack2(h00, h01);
            ha[mf][1] = pack2(h02, h03);
            ha[mf][2] = pack2(h10, h11);
            ha[mf][3] = pack2(h12, h13);
        }
        #pragma unroll
        for (int dt = 0; dt < 8; dt++) {
            const int c = ((dt * 8) ^ q8) + r;
            uint32_t fb0 = f0[c], fb1 = f1[c];
            mma_f16(oacc[0][dt], ha[0], fb0, fb1);
            mma_f16(oacc[1][dt], ha[1], fb0, fb1);
        }
    }

    // ---- epilogue: residual (L1/L2-hot re-read) + store; warp owns out[32 x 64] ----
    #pragma unroll
    for (int mf = 0; mf < 2; mf++) {
        const int gr0 = row0 + m0 + mf * 16 + r;
        const float* x0 = x + ((size_t)b * NN + gr0) * DD;
        const float* x1 = x0 + 8 * DD;
        float* o0 = out + ((size_t)b * NN + gr0) * DD;
        float* o1 = o0 + 8 * DD;
        #pragma unroll
        for (int dt = 0; dt < 8; dt++) {
            const int cc = dt * 8 + 2 * q;
            float2 r0v = *(const float2*)(x0 + cc);
            float2 r1v = *(const float2*)(x1 + cc);
            *(float2*)(o0 + cc) = make_float2(oacc[mf][dt][0] + r0v.x, oacc[mf][dt][1] + r0v.y);
            *(float2*)(o1 + cc) = make_float2(oacc[mf][dt][2] + r1v.x, oacc[mf][dt][3] + r1v.y);
        }
    }
}

// ======================= launch =======================
extern "C" void kernel_launch(void* const* d_in, const int* in_sizes, int n_in,
                              void* d_out, int out_size) {
    const float* x     = (const float*)d_in[0];
    const float* s     = (const float*)d_in[1];
    const float* W     = (const float*)d_in[2];
    const float* bias  = (const float*)d_in[3];
    const float* scale = (const float*)d_in[4];
    float* out = (float*)d_out;

    cudaFuncSetAttribute(k1_mma, cudaFuncAttributeMaxDynamicSharedMemorySize, K1_SMEM);
    k1_mma<<<dim3(TOT / 128), 256, K1_SMEM>>>(s, W, bias);

    k2_normalize<<<dim3(BB), 256>>>();

    cudaFuncSetAttribute(k3_main, cudaFuncAttributeMaxDynamicSharedMemorySize, K3_SMEM);
    k3_main<<<dim3(1024), 256, K3_SMEM>>>(x, scale, out);
}